// round 4
// baseline (speedup 1.0000x reference)
#include <cuda_runtime.h>
#include <cuda_bf16.h>

#define MOD 26
#define NN 64
#define BB 1024
#define NROWS (NN * NN)          // 4096 (l,i) rows
#define ROWPAD 32                // pad c-dim to 32 floats = 128B rows

// Scratch: Kp[l][p][i][c] table, 64*26*64*32 floats = 13.6 MB (L2-resident)
__device__ __align__(128) float g_Kp[NN * MOD * NN * ROWPAD];
// softmax(key_param), 4096*26
__device__ __align__(128) float g_kp[NROWS * MOD];

// ---------------------------------------------------------------------------
// Kernel 1: softmax over each length-26 row; also emit key_probs output tail.
// ---------------------------------------------------------------------------
__global__ void softmax_kernel(const float* __restrict__ key_param,
                               float* __restrict__ out_tail, int write_tail) {
    int r = blockIdx.x * blockDim.x + threadIdx.x;
    if (r >= NROWS) return;
    const float* x = key_param + r * MOD;
    float v[MOD];
    float mx = -1e30f;
#pragma unroll
    for (int k = 0; k < MOD; ++k) { v[k] = __ldg(x + k); mx = fmaxf(mx, v[k]); }
    float s = 0.f;
#pragma unroll
    for (int k = 0; k < MOD; ++k) { v[k] = expf(v[k] - mx); s += v[k]; }
    float inv = 1.f / s;
#pragma unroll
    for (int k = 0; k < MOD; ++k) {
        float p = v[k] * inv;
        g_kp[r * MOD + k] = p;
        if (write_tail) out_tail[r * MOD + k] = p;
    }
}

// ---------------------------------------------------------------------------
// Kernel 2: build Kp[l,p,i,c] = sum_k key_probs[l,i,k] * [(p*k) % 26 == c]
// One thread per (row, p, c) element: 4096*26*26 threads.
// ---------------------------------------------------------------------------
__global__ void build_kernel() {
    int t = blockIdx.x * blockDim.x + threadIdx.x;
    if (t >= NROWS * MOD * MOD) return;
    int c = t % MOD;
    int p = (t / MOD) % MOD;
    int r = t / (MOD * MOD);           // r = l*64 + i
    int l = r >> 6;
    int i = r & 63;
    const float* kp = g_kp + r * MOD;
    float acc = 0.f;
#pragma unroll
    for (int k = 0; k < MOD; ++k) {
        int m = (p * k) % MOD;
        acc += (m == c) ? __ldg(kp + k) : 0.f;
    }
    g_Kp[(((l * MOD) + p) * NN + i) * ROWPAD + c] = acc;
}

// ---------------------------------------------------------------------------
// Kernel 3: per-(b,i) chain of 63 circular convolutions.
//   dist <- normalize( circ_conv(dist, Kp[l, P[b,l], i, :]) )
// All conv indices compile-time -> dist/nd/pj fully register-resident.
// ---------------------------------------------------------------------------
__global__ void __launch_bounds__(128, 4)
chain_kernel(const int* __restrict__ P, float* __restrict__ out) {
    int t = blockIdx.x * blockDim.x + threadIdx.x;
    if (t >= BB * NN) return;
    int i = t & 63;
    int b = t >> 6;
    const int* Pb = P + b * NN;

    float dist[MOD];

    // init: l = 0
    {
        int p0 = __ldg(Pb);
        const float* row = g_Kp + (((0 * MOD) + p0) * NN + i) * ROWPAD;
        const float4* r4 = reinterpret_cast<const float4*>(row);
#pragma unroll
        for (int q = 0; q < 6; ++q) {
            float4 v = __ldg(r4 + q);
            dist[q * 4 + 0] = v.x; dist[q * 4 + 1] = v.y;
            dist[q * 4 + 2] = v.z; dist[q * 4 + 3] = v.w;
        }
        dist[24] = __ldg(row + 24);
        dist[25] = __ldg(row + 25);
    }

#pragma unroll 1
    for (int l = 1; l < NN; ++l) {
        int p = __ldg(Pb + l);
        const float* row = g_Kp + (((l * MOD) + p) * NN + i) * ROWPAD;
        float pj[MOD];
        const float4* r4 = reinterpret_cast<const float4*>(row);
#pragma unroll
        for (int q = 0; q < 6; ++q) {
            float4 v = __ldg(r4 + q);
            pj[q * 4 + 0] = v.x; pj[q * 4 + 1] = v.y;
            pj[q * 4 + 2] = v.z; pj[q * 4 + 3] = v.w;
        }
        pj[24] = __ldg(row + 24);
        pj[25] = __ldg(row + 25);

        float nd[MOD];
#pragma unroll
        for (int c = 0; c < MOD; ++c) nd[c] = 0.f;

#pragma unroll
        for (int m = 0; m < MOD; ++m) {
            float d = dist[m];
#pragma unroll
            for (int k = 0; k < MOD; ++k) {
                nd[(m + k) % MOD] += d * pj[k];   // compile-time index
            }
        }

        // normalize (clip is a no-op: all operands >= 0)
        float s = 0.f;
#pragma unroll
        for (int c = 0; c < MOD; ++c) s += nd[c];
        float inv = 1.f / s;
#pragma unroll
        for (int c = 0; c < MOD; ++c) dist[c] = nd[c] * inv;
    }

    float* o = out + (b * NN + i) * MOD;
#pragma unroll
    for (int c = 0; c < MOD; ++c) o[c] = __logf(dist[c] + 1e-12f);
}

// ---------------------------------------------------------------------------
extern "C" void kernel_launch(void* const* d_in, const int* in_sizes, int n_in,
                              void* d_out, int out_size) {
    const int*   P         = (const int*)d_in[0];          // (1024, 64) int32
    const float* key_param = (const float*)d_in[1];        // (4096, 26) f32
    float*       out       = (float*)d_out;

    const int log_elems = BB * NN * MOD;                   // 1703936
    const int kp_elems  = NROWS * MOD;                     // 106496
    int write_tail = (out_size >= log_elems + kp_elems) ? 1 : 0;
    float* out_tail = out + log_elems;

    softmax_kernel<<<(NROWS + 127) / 128, 128>>>(key_param, out_tail, write_tail);

    int build_threads = NROWS * MOD * MOD;                 // 2,768,896
    build_kernel<<<(build_threads + 255) / 256, 256>>>();

    chain_kernel<<<(BB * NN + 127) / 128, 128>>>(P, out);
}

// round 8
// speedup vs baseline: 3.1416x; 3.1416x over previous
#include <cuda_runtime.h>
#include <cuda_bf16.h>

#define MOD 26
#define NN 64
#define BB 1024
#define NROWS 4096

// Twiddles cos/sin(2*pi*t/26), t=0..25. __device__ constexpr: folded to
// immediates at compile-time index sites (FFMA-imm rt=1); copied to smem for
// runtime-index use in gbuild.
__device__ constexpr float H_COS[26] = {
    1.0f,         0.97094182f,  0.88545603f,  0.74851075f,  0.56806475f,
    0.35460489f,  0.12053668f, -0.12053668f, -0.35460489f, -0.56806475f,
   -0.74851075f, -0.88545603f, -0.97094182f, -1.0f,        -0.97094182f,
   -0.88545603f, -0.74851075f, -0.56806475f, -0.35460489f, -0.12053668f,
    0.12053668f,  0.35460489f,  0.56806475f,  0.74851075f,  0.88545603f,
    0.97094182f};
__device__ constexpr float H_SIN[26] = {
    0.0f,         0.23931566f,  0.46472317f,  0.66312266f,  0.82298387f,
    0.93501624f,  0.99270887f,  0.99270887f,  0.93501624f,  0.82298387f,
    0.66312266f,  0.46472317f,  0.23931566f,  0.0f,        -0.23931566f,
   -0.46472317f, -0.66312266f, -0.82298387f, -0.93501624f, -0.99270887f,
   -0.99270887f, -0.93501624f, -0.82298387f, -0.66312266f, -0.46472317f,
   -0.23931566f};

// softmax(key_param): 4096 x 26
__device__ float g_kp[NROWS * MOD];
// G[r=(l*64+i)][q]: DFT of prob row at frequency q. Row of 64 floats:
// [0..25] = re(q), [32..57] = im(q). Total 1 MB (L2 resident).
__device__ float g_G[NROWS * 64];

// ---------------------------------------------------------------------------
// Kernel 1: warp-per-row softmax; lanes 0..25 active. Also writes key_probs
// output tail.
// ---------------------------------------------------------------------------
__global__ void softmax_kernel(const float* __restrict__ key_param,
                               float* __restrict__ out_tail, int write_tail) {
    int gid  = blockIdx.x * 128 + threadIdx.x;
    int r    = gid >> 5;
    int lane = gid & 31;
    float v = -1e30f;
    if (lane < MOD) v = key_param[r * MOD + lane];
    float m = v;
#pragma unroll
    for (int o = 16; o; o >>= 1) m = fmaxf(m, __shfl_xor_sync(0xffffffffu, m, o));
    float e = (lane < MOD) ? __expf(v - m) : 0.f;
    float s = e;
#pragma unroll
    for (int o = 16; o; o >>= 1) s += __shfl_xor_sync(0xffffffffu, s, o);
    float p = e * (1.f / s);
    if (lane < MOD) {
        g_kp[r * MOD + lane] = p;
        if (write_tail) out_tail[r * MOD + lane] = p;
    }
}

// ---------------------------------------------------------------------------
// Kernel 2: G[r,q] = sum_k prob[r,k] * exp(-2*pi*i*(q*k mod 26)/26).
// Thread per (r, q). Incremental t avoids runtime mod; twiddles from smem.
// ---------------------------------------------------------------------------
__global__ void gbuild_kernel() {
    __shared__ float sc[MOD], ss[MOD];
    if (threadIdx.x == 0) {
#pragma unroll
        for (int t = 0; t < MOD; ++t) { sc[t] = H_COS[t]; ss[t] = H_SIN[t]; }
    }
    __syncthreads();
    int idx = blockIdx.x * 128 + threadIdx.x;
    if (idx >= NROWS * MOD) return;
    int q = idx % MOD;
    int r = idx / MOD;
    const float* pr = g_kp + r * MOD;
    float re = 0.f, im = 0.f;
    int t = 0;
#pragma unroll
    for (int k = 0; k < MOD; ++k) {
        float pk = pr[k];
        re = fmaf(pk, sc[t], re);
        im = fmaf(-pk, ss[t], im);
        t += q; if (t >= MOD) t -= MOD;
    }
    g_G[(r << 6) + q]      = re;
    g_G[(r << 6) + 32 + q] = im;
}

// ---------------------------------------------------------------------------
// Kernel 3: chain. Block = one i, 128 consecutive b. Stage all 64 G-rows for
// this i (14.3KB) + packed P bytes (8KB) into smem; 63 steps run entirely out
// of smem/registers. Bin j of step (l, p=P[b,l]) is G[l, i, (p*j)%26].
// Epilogue: length-26 irfft with immediate twiddles, normalize by 26*X0, log.
// ---------------------------------------------------------------------------
__global__ void __launch_bounds__(128)
chain_kernel(const int* __restrict__ P, float* __restrict__ out) {
    __shared__ float        sG[64 * 56];   // [l][s]: re at s=0..25, im at 28+s
    __shared__ unsigned int sP[16 * 128];  // [l/4][b_local]: 4 P bytes packed

    int tid = threadIdx.x;
    int i   = blockIdx.x >> 3;
    int b0  = (blockIdx.x & 7) << 7;

    // Stage G rows for this i.
    for (int m = tid; m < 64 * 56; m += 128) {
        int l = m / 56;
        int s = m - l * 56;
        const float* rowg = g_G + (((l << 6) + i) << 6);
        float v = 0.f;
        if (s < 26)                 v = rowg[s];
        else if (s >= 28 && s < 54) v = rowg[s + 4];  // 32 + (s-28)
        sG[m] = v;
    }
    // Stage P: pack 4 consecutive l's per uint.
    for (int m = tid; m < 2048; m += 128) {
        int bl = m & 127, l4 = m >> 7;
        const int4 pv = *reinterpret_cast<const int4*>(P + ((b0 + bl) << 6) + (l4 << 2));
        sP[(l4 << 7) + bl] = (unsigned)pv.x | ((unsigned)pv.y << 8) |
                             ((unsigned)pv.z << 16) | ((unsigned)pv.w << 24);
    }
    __syncthreads();

    float ar[14], ai[14];
    unsigned w = sP[tid];

    // l = 0: init accumulator from selected bins.
    {
        int p = w & 255;
        ar[0] = sG[0]; ai[0] = 0.f;
        int s = 0;
#pragma unroll
        for (int j = 1; j <= 13; ++j) {
            s += p; if (s >= MOD) s -= MOD;
            ar[j] = sG[s];
            ai[j] = sG[28 + s];
        }
    }

    auto step = [&](int l, int p) {
        int base = l * 56;
        ar[0] *= sG[base];                 // im(q=0) == 0 exactly
        int s = 0;
#pragma unroll
        for (int j = 1; j <= 13; ++j) {
            s += p; if (s >= MOD) s -= MOD;
            float gr = sG[base + s];
            float gi = sG[base + 28 + s];
            float nr = ar[j] * gr - ai[j] * gi;
            float ni = ar[j] * gi + ai[j] * gr;
            ar[j] = nr; ai[j] = ni;
        }
    };

    step(1, (w >> 8) & 255);
    step(2, (w >> 16) & 255);
    step(3, (w >> 24) & 255);
#pragma unroll 1
    for (int lb = 1; lb < 16; ++lb) {
        w = sP[(lb << 7) + tid];
        step(lb * 4 + 0,  w        & 255);
        step(lb * 4 + 1, (w >> 8)  & 255);
        step(lb * 4 + 2, (w >> 16) & 255);
        step(lb * 4 + 3, (w >> 24) & 255);
    }

    // Epilogue: irfft + normalize (+eps) + log.
    // sum_c dist[c] = 26 * X0 exactly, so normalize by 26*ar[0].
    float inv = 1.f / (26.f * ar[0]);
    float* o = out + (((b0 + tid) << 6) + i) * MOD;
#pragma unroll
    for (int c = 0; c < MOD; ++c) {
        float v = ar[0] + ((c & 1) ? -ar[13] : ar[13]);  // im13 == 0 exactly
#pragma unroll
        for (int j = 1; j <= 12; ++j) {
            const int t = (j * c) % MOD;                  // compile-time
            v = fmaf(ar[j],  2.f * H_COS[t], v);          // FFMA-imm
            v = fmaf(ai[j], -2.f * H_SIN[t], v);
        }
        o[c] = __logf(fmaf(v, inv, 1e-12f));
    }
}

// ---------------------------------------------------------------------------
extern "C" void kernel_launch(void* const* d_in, const int* in_sizes, int n_in,
                              void* d_out, int out_size) {
    const int*   P         = (const int*)d_in[0];    // (1024, 64) int32
    const float* key_param = (const float*)d_in[1];  // (4096, 26) f32
    float*       out       = (float*)d_out;

    const int log_elems = BB * NN * MOD;             // 1,703,936
    const int kp_elems  = NROWS * MOD;               // 106,496
    int write_tail = (out_size >= log_elems + kp_elems) ? 1 : 0;

    softmax_kernel<<<1024, 128>>>(key_param, out + log_elems, write_tail);
    gbuild_kernel<<<(NROWS * MOD + 127) / 128, 128>>>();
    chain_kernel<<<512, 128>>>(P, out);
}

// round 9
// speedup vs baseline: 4.7962x; 1.5267x over previous
#include <cuda_runtime.h>
#include <cuda_bf16.h>

#define MOD 26
#define NN 64
#define BB 1024
#define NROWS 4096

// Twiddles cos/sin(2*pi*t/26). Compile-time index sites fold to FFMA-imm;
// dynamic-index use goes through an smem copy.
__device__ constexpr float H_COS[26] = {
    1.0f,         0.97094182f,  0.88545603f,  0.74851075f,  0.56806475f,
    0.35460489f,  0.12053668f, -0.12053668f, -0.35460489f, -0.56806475f,
   -0.74851075f, -0.88545603f, -0.97094182f, -1.0f,        -0.97094182f,
   -0.88545603f, -0.74851075f, -0.56806475f, -0.35460489f, -0.12053668f,
    0.12053668f,  0.35460489f,  0.56806475f,  0.74851075f,  0.88545603f,
    0.97094182f};
__device__ constexpr float H_SIN[26] = {
    0.0f,         0.23931566f,  0.46472317f,  0.66312266f,  0.82298387f,
    0.93501624f,  0.99270887f,  0.99270887f,  0.93501624f,  0.82298387f,
    0.66312266f,  0.46472317f,  0.23931566f,  0.0f,        -0.23931566f,
   -0.46472317f, -0.66312266f, -0.82298387f, -0.93501624f, -0.99270887f,
   -0.99270887f, -0.93501624f, -0.82298387f, -0.66312266f, -0.46472317f,
   -0.23931566f};

// G[r=(l*64+i)][q] = DFT_q(softmax row r), interleaved (re,im). 852 KB.
__device__ float2 g_G2[NROWS * MOD];

// ---------------------------------------------------------------------------
// Kernel 1 (fused): warp-per-row softmax + 26-point DFT via shfl broadcast.
// Also writes the key_probs output tail.
// ---------------------------------------------------------------------------
__global__ void __launch_bounds__(128)
prep_kernel(const float* __restrict__ key_param,
            float* __restrict__ out_tail, int write_tail) {
    __shared__ float sc[MOD], ss[MOD];
    if (threadIdx.x < MOD) {
        sc[threadIdx.x] = H_COS[threadIdx.x];
        ss[threadIdx.x] = H_SIN[threadIdx.x];
    }
    __syncthreads();

    int warp = threadIdx.x >> 5, lane = threadIdx.x & 31;
    int r = blockIdx.x * 4 + warp;

    float v = (lane < MOD) ? key_param[r * MOD + lane] : -1e30f;
    float m = v;
#pragma unroll
    for (int o = 16; o; o >>= 1) m = fmaxf(m, __shfl_xor_sync(0xffffffffu, m, o));
    float e = (lane < MOD) ? __expf(v - m) : 0.f;
    float s = e;
#pragma unroll
    for (int o = 16; o; o >>= 1) s += __shfl_xor_sync(0xffffffffu, s, o);
    float p = e * (1.f / s);
    if (lane < MOD && write_tail) out_tail[r * MOD + lane] = p;

    // DFT bin q = lane: G = sum_k p_k * exp(-2*pi*i*q*k/26)
    int q = (lane < MOD) ? lane : 0;
    float re = 0.f, im = 0.f;
    int t = 0;
#pragma unroll
    for (int k = 0; k < MOD; ++k) {
        float pk = __shfl_sync(0xffffffffu, p, k);
        re = fmaf(pk, sc[t], re);
        im = fmaf(-pk, ss[t], im);
        t += q; if (t >= MOD) t -= MOD;
    }
    if (lane < MOD) g_G2[r * MOD + lane] = make_float2(re, im);
}

// ---------------------------------------------------------------------------
// Kernel 2: chain. Block = one i, 128 consecutive b. Stage 64 G rows (float2,
// 14.3KB) + packed P (8KB); 63 steps of 13 complex mults run from smem/regs.
// Early-exit when all non-DC bins hit exact fp32 zero (output then provably
// the uniform distribution regardless of remaining factors).
// ---------------------------------------------------------------------------
__global__ void __launch_bounds__(128)
chain_kernel(const int* __restrict__ P, float* __restrict__ out) {
    __shared__ float2   sG[NN * 28];    // [l*28 + s], s<26 valid
    __shared__ unsigned sP[16 * 128];   // [l/4][b_local]
    __shared__ float    sOut[128 * 28]; // epilogue staging

    int tid = threadIdx.x;
    int i   = blockIdx.x >> 3;
    int b0  = (blockIdx.x & 7) << 7;

    for (int m = tid; m < NN * 32; m += 128) {
        int l = m >> 5, s = m & 31;
        if (s < MOD) sG[l * 28 + s] = g_G2[((l << 6) | i) * MOD + s];
    }
    for (int m = tid; m < 2048; m += 128) {
        int bl = m & 127, l4 = m >> 7;
        int4 pv = *reinterpret_cast<const int4*>(P + ((b0 + bl) << 6) + (l4 << 2));
        sP[(l4 << 7) + bl] = (unsigned)pv.x | ((unsigned)pv.y << 8) |
                             ((unsigned)pv.z << 16) | ((unsigned)pv.w << 24);
    }
    __syncthreads();

    float ar[14], ai[14];
    unsigned w = sP[tid];

    { // l = 0 init
        unsigned p = w & 255u;
        ar[0] = sG[0].x; ai[0] = 0.f;
        unsigned s = 0;
#pragma unroll
        for (int j = 1; j <= 13; ++j) {
            s += p; s = min(s, s - (unsigned)MOD);
            float2 g = sG[s];
            ar[j] = g.x; ai[j] = g.y;
        }
    }

    auto step = [&](int l, unsigned p) {
        const float2* gl = sG + l * 28;
        ar[0] *= gl[0].x;                       // im(DC) == 0 exactly
        unsigned s = 0;
#pragma unroll
        for (int j = 1; j <= 13; ++j) {
            s += p; s = min(s, s - (unsigned)MOD);
            float2 g = gl[s];
            float nr = fmaf(ar[j], g.x, -ai[j] * g.y);
            float ni = fmaf(ar[j], g.y,  ai[j] * g.x);
            ar[j] = nr; ai[j] = ni;
        }
    };

    step(1, (w >> 8) & 255u);
    step(2, (w >> 16) & 255u);
    step(3, (w >> 24) & 255u);

    bool exited = false;
#pragma unroll 1
    for (int lb = 1; lb < 16; ++lb) {
        // Early exit: all non-DC bins exactly (+/-)0 in every lane of the warp.
        unsigned nz = 0;
#pragma unroll
        for (int j = 1; j <= 13; ++j)
            nz |= __float_as_uint(ar[j]) | __float_as_uint(ai[j]);
        if (__all_sync(0xffffffffu, (nz << 1) == 0u)) { exited = true; break; }

        w = sP[(lb << 7) + tid];
        step(lb * 4 + 0,  w         & 255u);
        step(lb * 4 + 1, (w >> 8)   & 255u);
        step(lb * 4 + 2, (w >> 16)  & 255u);
        step(lb * 4 + 3, (w >> 24)  & 255u);
    }

    // Epilogue: irfft + normalize + log, staged to smem.
    float* so = sOut + tid * 28;
    if (exited) {
        // bins all zero -> dist is exactly uniform after normalization.
        float val = __logf(1.0f / 26.0f + 1e-12f);
#pragma unroll
        for (int c = 0; c < MOD; ++c) so[c] = val;
    } else {
        float inv = 1.f / (26.f * ar[0]);
#pragma unroll
        for (int c = 0; c < MOD; ++c) {
            float v = ar[0] + ((c & 1) ? -ar[13] : ar[13]);  // im13 == 0 exactly
#pragma unroll
            for (int j = 1; j <= 12; ++j) {
                const int t = (j * c) % MOD;                 // compile-time
                v = fmaf(ar[j],  2.f * H_COS[t], v);         // FFMA-imm
                v = fmaf(ai[j], -2.f * H_SIN[t], v);
            }
            so[c] = __logf(fmaf(v, inv, 1e-12f));
        }
    }
    __syncthreads();

    // Coalesced-ish writeout: warp per row, lanes 0..25 cover one 104B row.
    int warpId = tid >> 5, lane = tid & 31;
    if (lane < MOD) {
#pragma unroll 1
        for (int k = 0; k < 32; ++k) {
            int r = (warpId << 5) + k;
            out[(((b0 + r) << 6) | i) * MOD + lane] = sOut[r * 28 + lane];
        }
    }
}

// ---------------------------------------------------------------------------
extern "C" void kernel_launch(void* const* d_in, const int* in_sizes, int n_in,
                              void* d_out, int out_size) {
    const int*   P         = (const int*)d_in[0];    // (1024, 64) int32
    const float* key_param = (const float*)d_in[1];  // (4096, 26) f32
    float*       out       = (float*)d_out;

    const int log_elems = BB * NN * MOD;             // 1,703,936
    const int kp_elems  = NROWS * MOD;               // 106,496
    int write_tail = (out_size >= log_elems + kp_elems) ? 1 : 0;

    prep_kernel<<<NROWS / 4, 128>>>(key_param, out + log_elems, write_tail);
    chain_kernel<<<512, 128>>>(P, out);
}

// round 10
// speedup vs baseline: 5.2871x; 1.1024x over previous
#include <cuda_runtime.h>
#include <cuda_bf16.h>

#define MOD 26
#define NN 64
#define BB 1024
#define NROWS 4096

// Twiddles cos/sin(2*pi*t/26). Compile-time index sites fold to FFMA-imm;
// dynamic-index use goes through an smem copy.
__device__ constexpr float H_COS[26] = {
    1.0f,         0.97094182f,  0.88545603f,  0.74851075f,  0.56806475f,
    0.35460489f,  0.12053668f, -0.12053668f, -0.35460489f, -0.56806475f,
   -0.74851075f, -0.88545603f, -0.97094182f, -1.0f,        -0.97094182f,
   -0.88545603f, -0.74851075f, -0.56806475f, -0.35460489f, -0.12053668f,
    0.12053668f,  0.35460489f,  0.56806475f,  0.74851075f,  0.88545603f,
    0.97094182f};
__device__ constexpr float H_SIN[26] = {
    0.0f,         0.23931566f,  0.46472317f,  0.66312266f,  0.82298387f,
    0.93501624f,  0.99270887f,  0.99270887f,  0.93501624f,  0.82298387f,
    0.66312266f,  0.46472317f,  0.23931566f,  0.0f,        -0.23931566f,
   -0.46472317f, -0.66312266f, -0.82298387f, -0.93501624f, -0.99270887f,
   -0.99270887f, -0.93501624f, -0.82298387f, -0.66312266f, -0.46472317f,
   -0.23931566f};

// G[r=(l*64+i)][q] = DFT_q(softmax row r), interleaved (re,im). 852 KB, L2.
__device__ float2 g_G2[NROWS * MOD];

// ---------------------------------------------------------------------------
// Kernel 1 (fused): warp-per-row softmax + 26-point DFT via shfl broadcast.
// Also writes the key_probs output tail.
// ---------------------------------------------------------------------------
__global__ void __launch_bounds__(128)
prep_kernel(const float* __restrict__ key_param,
            float* __restrict__ out_tail, int write_tail) {
    __shared__ float sc[MOD], ss[MOD];
    if (threadIdx.x < MOD) {
        sc[threadIdx.x] = H_COS[threadIdx.x];
        ss[threadIdx.x] = H_SIN[threadIdx.x];
    }
    __syncthreads();

    int warp = threadIdx.x >> 5, lane = threadIdx.x & 31;
    int r = blockIdx.x * 4 + warp;

    float v = (lane < MOD) ? key_param[r * MOD + lane] : -1e30f;
    float m = v;
#pragma unroll
    for (int o = 16; o; o >>= 1) m = fmaxf(m, __shfl_xor_sync(0xffffffffu, m, o));
    float e = (lane < MOD) ? __expf(v - m) : 0.f;
    float s = e;
#pragma unroll
    for (int o = 16; o; o >>= 1) s += __shfl_xor_sync(0xffffffffu, s, o);
    float p = e * (1.f / s);
    if (lane < MOD && write_tail) out_tail[r * MOD + lane] = p;

    int q = (lane < MOD) ? lane : 0;
    float re = 0.f, im = 0.f;
    int t = 0;
#pragma unroll
    for (int k = 0; k < MOD; ++k) {
        float pk = __shfl_sync(0xffffffffu, p, k);
        re = fmaf(pk, sc[t], re);
        im = fmaf(-pk, ss[t], im);
        t += q; if (t >= MOD) t -= MOD;
    }
    if (lane < MOD) g_G2[r * MOD + lane] = make_float2(re, im);
}

// ---------------------------------------------------------------------------
// Kernel 2: chain. Block = one i x 64 b. Thread pair (2k, 2k+1) owns one
// (b,i) chain, split by frequency bins: half0 -> bins 0(DC)..6, half1 -> 7..13.
// SoA G in smem at stride 32 (bank == s, conflict-free LDS.32).
// DC processed as a regular complex bin (its imag is exactly +0) -> uniform.
// Early-exit when all non-DC bins in the warp are exact fp32 zero.
// Epilogue: pair-exchange via shfl, irfft with immediate twiddles (odd-j
// pre-negation folds the c+13 half), staged smem writeout.
// ---------------------------------------------------------------------------
__global__ void __launch_bounds__(128, 7)
chain_kernel(const int* __restrict__ P, float* __restrict__ out) {
    __shared__ float         sGr[NN * 32];   // [l*32 + s]
    __shared__ float         sGi[NN * 32];
    __shared__ unsigned      sP[16 * 64];    // [l/4][b_local]
    __shared__ unsigned char sStart[64];     // [half*26 + p] -> (7p*half)%26
    __shared__ float         sOut[64 * 28];

    int tid = threadIdx.x;
    int i   = blockIdx.x >> 4;
    int b0  = (blockIdx.x & 15) << 6;

    if (tid < 52)
        sStart[tid] = (tid < 26) ? 0 : (unsigned char)((7 * (tid - 26)) % MOD);

    for (int m = tid; m < NN * 32; m += 128) {
        int l = m >> 5, s = m & 31;
        if (s < MOD) {
            float2 g = g_G2[((l << 6) | i) * MOD + s];
            sGr[m] = g.x; sGi[m] = g.y;
        }
    }
    for (int m = tid; m < 1024; m += 128) {
        int bl = m & 63, l4 = m >> 6;
        int4 pv = *reinterpret_cast<const int4*>(P + ((b0 + bl) << 6) + (l4 << 2));
        sP[(l4 << 6) + bl] = (unsigned)pv.x | ((unsigned)pv.y << 8) |
                             ((unsigned)pv.z << 16) | ((unsigned)pv.w << 24);
    }
    __syncthreads();

    int bl    = tid >> 1;
    int half  = tid & 1;
    int hbase = half * MOD;

    float ar[7], ai[7];
    unsigned w = sP[bl];

    { // l = 0: init bins jstart..jstart+6, jstart = 7*half
        unsigned p = w & 255u;
        unsigned s = sStart[hbase + p];
#pragma unroll
        for (int k = 0; k < 7; ++k) {
            ar[k] = sGr[s]; ai[k] = sGi[s];
            s += p; s = min(s, s - (unsigned)MOD);
        }
    }

    auto step = [&](int l, unsigned p) {
        const int base = l << 5;
        unsigned s = sStart[hbase + p];
#pragma unroll
        for (int k = 0; k < 7; ++k) {
            float gr = sGr[base + s];
            float gi = sGi[base + s];
            float nr = fmaf(ar[k], gr, -ai[k] * gi);
            float ni = fmaf(ar[k], gi,  ai[k] * gr);
            ar[k] = nr; ai[k] = ni;
            s += p; s = min(s, s - (unsigned)MOD);
        }
    };

    step(1, (w >> 8) & 255u);
    step(2, (w >> 16) & 255u);
    step(3, (w >> 24) & 255u);

    bool exited = false;
#pragma unroll 1
    for (int lb = 1; lb < 16; ++lb) {
        // Exit iff every non-DC bin in the warp is exactly +/-0.
        unsigned nz = 0;
#pragma unroll
        for (int k = 1; k < 7; ++k)
            nz |= __float_as_uint(ar[k]) | __float_as_uint(ai[k]);
        unsigned nz0 = __float_as_uint(ar[0]) | __float_as_uint(ai[0]);
        nz |= half ? nz0 : 0u;    // half0's k=0 is the (never-zero) DC bin
        if (__all_sync(0xffffffffu, (nz << 1) == 0u)) { exited = true; break; }

        w = sP[(lb << 6) + bl];
        step(lb * 4 + 0,  w         & 255u);
        step(lb * 4 + 1, (w >> 8)   & 255u);
        step(lb * 4 + 2, (w >> 16)  & 255u);
        step(lb * 4 + 3, (w >> 24)  & 255u);
    }

    float* so = sOut + bl * 28 + half * 13;
    if (exited) {
        float val = __logf(1.0f / 26.0f + 1e-12f);
#pragma unroll
        for (int c0 = 0; c0 < 13; ++c0) so[c0] = val;
    } else {
        // Pair exchange: assemble all 14 bins in every thread.
        float br[14], bi[14];
#pragma unroll
        for (int k = 0; k < 7; ++k) {
            float xr = __shfl_xor_sync(0xffffffffu, ar[k], 1);
            float xi = __shfl_xor_sync(0xffffffffu, ai[k], 1);
            br[k]     = half ? xr    : ar[k];
            bi[k]     = half ? xi    : ai[k];
            br[7 + k] = half ? ar[k] : xr;
            bi[7 + k] = half ? ai[k] : xi;
        }
        // c = c0 + 13*half. Twiddle (j*c)%26 = (j*c0)%26 + 13*(j&1)*half:
        // the +13 flips both cos and sin -> pre-negate odd-j bins for half1.
        float sg = half ? -1.f : 1.f;
#pragma unroll
        for (int j = 1; j < 14; j += 2) { br[j] *= sg; bi[j] *= sg; }

        float inv = 1.f / (26.f * br[0]);
#pragma unroll
        for (int c0 = 0; c0 < 13; ++c0) {
            float v = br[0] + ((c0 & 1) ? -br[13] : br[13]);
#pragma unroll
            for (int j = 1; j <= 12; ++j) {
                const int t = (j * c0) % MOD;             // compile-time
                v = fmaf(br[j],  2.f * H_COS[t], v);      // FFMA-imm
                v = fmaf(bi[j], -2.f * H_SIN[t], v);
            }
            so[c0] = __logf(fmaf(v, inv, 1e-12f));
        }
    }
    __syncthreads();

    // Coalesced writeout: warp per 16 rows, lanes 0..25 per 104B row.
    int warp = tid >> 5, lane = tid & 31;
    if (lane < MOD) {
#pragma unroll 1
        for (int k = 0; k < 16; ++k) {
            int r = (warp << 4) + k;
            out[(((b0 + r) << 6) | i) * MOD + lane] = sOut[r * 28 + lane];
        }
    }
}

// ---------------------------------------------------------------------------
extern "C" void kernel_launch(void* const* d_in, const int* in_sizes, int n_in,
                              void* d_out, int out_size) {
    const int*   P         = (const int*)d_in[0];    // (1024, 64) int32
    const float* key_param = (const float*)d_in[1];  // (4096, 26) f32
    float*       out       = (float*)d_out;

    const int log_elems = BB * NN * MOD;             // 1,703,936
    const int kp_elems  = NROWS * MOD;               // 106,496
    int write_tail = (out_size >= log_elems + kp_elems) ? 1 : 0;

    prep_kernel<<<NROWS / 4, 128>>>(key_param, out + log_elems, write_tail);
    chain_kernel<<<1024, 128>>>(P, out);
}

// round 11
// speedup vs baseline: 6.0424x; 1.1429x over previous
#include <cuda_runtime.h>
#include <cuda_bf16.h>

#define MOD 26
#define NN 64
#define BB 1024
#define NROWS 4096

__device__ constexpr float H_COS[26] = {
    1.0f,         0.97094182f,  0.88545603f,  0.74851075f,  0.56806475f,
    0.35460489f,  0.12053668f, -0.12053668f, -0.35460489f, -0.56806475f,
   -0.74851075f, -0.88545603f, -0.97094182f, -1.0f,        -0.97094182f,
   -0.88545603f, -0.74851075f, -0.56806475f, -0.35460489f, -0.12053668f,
    0.12053668f,  0.35460489f,  0.56806475f,  0.74851075f,  0.88545603f,
    0.97094182f};
__device__ constexpr float H_SIN[26] = {
    0.0f,         0.23931566f,  0.46472317f,  0.66312266f,  0.82298387f,
    0.93501624f,  0.99270887f,  0.99270887f,  0.93501624f,  0.82298387f,
    0.66312266f,  0.46472317f,  0.23931566f,  0.0f,        -0.23931566f,
   -0.46472317f, -0.66312266f, -0.82298387f, -0.93501624f, -0.99270887f,
   -0.99270887f, -0.93501624f, -0.82298387f, -0.66312266f, -0.46472317f,
   -0.23931566f};

// G[r=(l*64+i)][q] = DFT_q(softmax row r), interleaved (re,im). 852 KB, L2.
__device__ float2 g_G2[NROWS * MOD];

// ---------------------------------------------------------------------------
// Kernel 1 (fused): warp-per-row softmax + 26-point DFT via shfl broadcast.
// ---------------------------------------------------------------------------
__global__ void __launch_bounds__(128)
prep_kernel(const float* __restrict__ key_param,
            float* __restrict__ out_tail, int write_tail) {
    __shared__ float sc[MOD], ss[MOD];
    if (threadIdx.x < MOD) {
        sc[threadIdx.x] = H_COS[threadIdx.x];
        ss[threadIdx.x] = H_SIN[threadIdx.x];
    }
    __syncthreads();

    int warp = threadIdx.x >> 5, lane = threadIdx.x & 31;
    int r = blockIdx.x * 4 + warp;

    float v = (lane < MOD) ? key_param[r * MOD + lane] : -1e30f;
    float m = v;
#pragma unroll
    for (int o = 16; o; o >>= 1) m = fmaxf(m, __shfl_xor_sync(0xffffffffu, m, o));
    float e = (lane < MOD) ? __expf(v - m) : 0.f;
    float s = e;
#pragma unroll
    for (int o = 16; o; o >>= 1) s += __shfl_xor_sync(0xffffffffu, s, o);
    float p = e * (1.f / s);
    if (lane < MOD && write_tail) out_tail[r * MOD + lane] = p;

    int q = (lane < MOD) ? lane : 0;
    float re = 0.f, im = 0.f;
    int t = 0;
#pragma unroll
    for (int k = 0; k < MOD; ++k) {
        float pk = __shfl_sync(0xffffffffu, p, k);
        re = fmaf(pk, sc[t], re);
        im = fmaf(-pk, ss[t], im);
        t += q; if (t >= MOD) t -= MOD;
    }
    if (lane < MOD) g_G2[r * MOD + lane] = make_float2(re, im);
}

// ---------------------------------------------------------------------------
// Kernel 2: chain. Block = one i x 64 b, 256 threads. Four threads per (b,i)
// chain, bins split by quarters with starts {0,4,7,10} (4 bins each, j=7 and
// j=10 duplicated). Per-(quarter,p) LUT packs 4 byte-offsets -> 1 LDS + byte
// extract per step, no serial index chain. SoA G (conflict-free LDS.32).
// Early-exit when all non-DC bins in the warp are exact fp32 zero.
// Epilogue streams bins via shfl into 13 c-accumulators (immediate twiddles,
// odd-j pre-negation folds the c+13 half); quarters 0/1 store, 2/3 shadow.
// ---------------------------------------------------------------------------
__global__ void __launch_bounds__(256, 7)
chain_kernel(const int* __restrict__ P, float* __restrict__ out) {
    __shared__ float    sG[2 * NN * 32];   // re at [l*32+s], im at +2048 floats
    __shared__ unsigned sP[16 * 64];       // [l/4][b_local]
    __shared__ unsigned sIdx[4 * 26];      // [q*26+p]: 4 packed byte-offsets
    __shared__ float    sOut[64 * 28];

    int tid = threadIdx.x;
    int i   = blockIdx.x >> 4;
    int b0  = (blockIdx.x & 15) << 6;

    if (tid < 104) {
        int q = tid / 26, p = tid - q * 26;
        int js = (q * 10 + 2) / 3;          // {0,4,7,10}
        unsigned v = 0;
#pragma unroll
        for (int k = 0; k < 4; ++k)
            v |= (unsigned)((((js + k) * p) % MOD) * 4) << (8 * k);
        sIdx[tid] = v;
    }
    for (int m = tid; m < NN * 32; m += 256) {
        int l = m >> 5, s = m & 31;
        if (s < MOD) {
            float2 g = g_G2[((l << 6) | i) * MOD + s];
            sG[m] = g.x; sG[2048 + m] = g.y;
        }
    }
    for (int m = tid; m < 1024; m += 256) {
        int bl = m & 63, l4 = m >> 6;
        int4 pv = *reinterpret_cast<const int4*>(P + ((b0 + bl) << 6) + (l4 << 2));
        sP[(l4 << 6) + bl] = (unsigned)pv.x | ((unsigned)pv.y << 8) |
                             ((unsigned)pv.z << 16) | ((unsigned)pv.w << 24);
    }
    __syncthreads();

    int bl = tid >> 2;
    int q  = tid & 3;
    int hq = q * 26;

    float ar[4], ai[4];
    unsigned w = sP[bl];

    { // l = 0 init
        unsigned idx = sIdx[hq + (w & 255u)];
#pragma unroll
        for (int k = 0; k < 4; ++k) {
            unsigned off = (idx >> (8 * k)) & 255u;
            const float* gp = (const float*)((const char*)sG + off);
            ar[k] = gp[0]; ai[k] = gp[2048];
        }
    }

    auto step = [&](int l, unsigned p) {
        unsigned idx = sIdx[hq + p];
        const char* base = (const char*)sG + (l << 7);
#pragma unroll
        for (int k = 0; k < 4; ++k) {
            unsigned off = (idx >> (8 * k)) & 255u;
            const float* gp = (const float*)(base + off);
            float gr = gp[0];
            float gi = gp[2048];
            float nr = fmaf(ar[k], gr, -ai[k] * gi);
            float ni = fmaf(ar[k], gi,  ai[k] * gr);
            ar[k] = nr; ai[k] = ni;
        }
    };

    step(1, (w >> 8) & 255u);
    step(2, (w >> 16) & 255u);
    step(3, (w >> 24) & 255u);

    bool exited = false;
#pragma unroll 1
    for (int lb = 1; lb < 16; ++lb) {
        unsigned nz = __float_as_uint(ar[1]) | __float_as_uint(ai[1]) |
                      __float_as_uint(ar[2]) | __float_as_uint(ai[2]) |
                      __float_as_uint(ar[3]) | __float_as_uint(ai[3]);
        unsigned nz0 = __float_as_uint(ar[0]) | __float_as_uint(ai[0]);
        nz |= q ? nz0 : 0u;      // quarter0's k=0 is the (never-zero) DC bin
        if (__all_sync(0xffffffffu, (nz << 1) == 0u)) { exited = true; break; }

        w = sP[(lb << 6) + bl];
        step(lb * 4 + 0,  w         & 255u);
        step(lb * 4 + 1, (w >> 8)   & 255u);
        step(lb * 4 + 2, (w >> 16)  & 255u);
        step(lb * 4 + 3, (w >> 24)  & 255u);
    }

    int lane  = tid & 31;
    int half  = q & 1;
    float* so = sOut + bl * 28 + half * 13;

    if (exited) {
        if (q < 2) {
            float val = __logf(1.0f / 26.0f + 1e-12f);
#pragma unroll
            for (int c0 = 0; c0 < 13; ++c0) so[c0] = val;
        }
    } else {
        unsigned gb = lane & ~3u;
        float sg = half ? -1.f : 1.f;
        float v[13];

        // j = 0 (DC, owner q0 k0): coefficient 1, imag exactly 0.
        float b0r = __shfl_sync(0xffffffffu, ar[0], gb);
#pragma unroll
        for (int c0 = 0; c0 < 13; ++c0) v[c0] = b0r;

        // j = 1..12: coefficient 2; odd-j pre-negated for the c+13 half.
#define EPI_J(J, QJ, KJ)                                                      \
        {                                                                     \
            float r_ = __shfl_sync(0xffffffffu, ar[KJ], gb + QJ);             \
            float i_ = __shfl_sync(0xffffffffu, ai[KJ], gb + QJ);             \
            if ((J) & 1) { r_ *= sg; i_ *= sg; }                              \
            _Pragma("unroll")                                                 \
            for (int c0 = 0; c0 < 13; ++c0) {                                 \
                v[c0] = fmaf(r_,  2.f * H_COS[((J) * c0) % MOD], v[c0]);      \
                v[c0] = fmaf(i_, -2.f * H_SIN[((J) * c0) % MOD], v[c0]);      \
            }                                                                 \
        }
        EPI_J(1, 0, 1)  EPI_J(2, 0, 2)  EPI_J(3, 0, 3)
        EPI_J(4, 1, 0)  EPI_J(5, 1, 1)  EPI_J(6, 1, 2)  EPI_J(7, 1, 3)
        EPI_J(8, 2, 1)  EPI_J(9, 2, 2)  EPI_J(10, 2, 3)
        EPI_J(11, 3, 1) EPI_J(12, 3, 2)
#undef EPI_J
        // j = 13 (Nyquist, owner q3 k3): coefficient 1, cos = +/-1, sin = 0.
        {
            float r13 = __shfl_sync(0xffffffffu, ar[3], gb + 3) * sg;
#pragma unroll
            for (int c0 = 0; c0 < 13; ++c0)
                v[c0] += (c0 & 1) ? -r13 : r13;
        }

        if (q < 2) {
            float inv = 1.f / (26.f * b0r);
#pragma unroll
            for (int c0 = 0; c0 < 13; ++c0)
                so[c0] = __logf(fmaf(v[c0], inv, 1e-12f));
        }
    }
    __syncthreads();

    // Coalesced writeout: 8 warps x 8 rows, lanes 0..25 per 104B row.
    int warp = tid >> 5;
    if (lane < MOD) {
#pragma unroll 1
        for (int k = 0; k < 8; ++k) {
            int r = (warp << 3) + k;
            out[(((b0 + r) << 6) | i) * MOD + lane] = sOut[r * 28 + lane];
        }
    }
}

// ---------------------------------------------------------------------------
extern "C" void kernel_launch(void* const* d_in, const int* in_sizes, int n_in,
                              void* d_out, int out_size) {
    const int*   P         = (const int*)d_in[0];    // (1024, 64) int32
    const float* key_param = (const float*)d_in[1];  // (4096, 26) f32
    float*       out       = (float*)d_out;

    const int log_elems = BB * NN * MOD;             // 1,703,936
    const int kp_elems  = NROWS * MOD;               // 106,496
    int write_tail = (out_size >= log_elems + kp_elems) ? 1 : 0;

    prep_kernel<<<NROWS / 4, 128>>>(key_param, out + log_elems, write_tail);
    chain_kernel<<<1024, 256>>>(P, out);
}

// round 15
// speedup vs baseline: 8.0179x; 1.3269x over previous
#include <cuda_runtime.h>
#include <cuda_bf16.h>

#define MOD 26
#define NN 64
#define BB 1024
#define NROWS 4096

__device__ constexpr float H_COS[26] = {
    1.0f,         0.97094182f,  0.88545603f,  0.74851075f,  0.56806475f,
    0.35460489f,  0.12053668f, -0.12053668f, -0.35460489f, -0.56806475f,
   -0.74851075f, -0.88545603f, -0.97094182f, -1.0f,        -0.97094182f,
   -0.88545603f, -0.74851075f, -0.56806475f, -0.35460489f, -0.12053668f,
    0.12053668f,  0.35460489f,  0.56806475f,  0.74851075f,  0.88545603f,
    0.97094182f};
__device__ constexpr float H_SIN[26] = {
    0.0f,         0.23931566f,  0.46472317f,  0.66312266f,  0.82298387f,
    0.93501624f,  0.99270887f,  0.99270887f,  0.93501624f,  0.82298387f,
    0.66312266f,  0.46472317f,  0.23931566f,  0.0f,        -0.23931566f,
   -0.46472317f, -0.66312266f, -0.82298387f, -0.93501624f, -0.99270887f,
   -0.99270887f, -0.93501624f, -0.82298387f, -0.66312266f, -0.46472317f,
   -0.23931566f};

// Exit threshold: |bin| < 1e-8 for all non-DC bins. Since every |G_q| <= 1,
// the reference's final bins are then also <= 1e-8, so emitting the exact
// uniform distribution is within ~2e-6 log-relative error of the reference
// for ANY input. bits(1e-8) = 0x322BCC77; compared against (OR of bits)<<1.
#define EXIT_TH2 (0x322BCC77u << 1)

// G[r=(l*64+i)][q] = DFT_q(softmax row r), interleaved (re,im). 852 KB, L2.
__device__ float2 g_G2[NROWS * MOD];

// ---------------------------------------------------------------------------
// Kernel 1 (fused): warp-per-row softmax + 26-point DFT via shfl broadcast.
// ---------------------------------------------------------------------------
__global__ void __launch_bounds__(128)
prep_kernel(const float* __restrict__ key_param,
            float* __restrict__ out_tail, int write_tail) {
    __shared__ float sc[MOD], ss[MOD];
    if (threadIdx.x < MOD) {
        sc[threadIdx.x] = H_COS[threadIdx.x];
        ss[threadIdx.x] = H_SIN[threadIdx.x];
    }
    __syncthreads();

    int warp = threadIdx.x >> 5, lane = threadIdx.x & 31;
    int r = blockIdx.x * 4 + warp;

    float v = (lane < MOD) ? key_param[r * MOD + lane] : -1e30f;
    float m = v;
#pragma unroll
    for (int o = 16; o; o >>= 1) m = fmaxf(m, __shfl_xor_sync(0xffffffffu, m, o));
    float e = (lane < MOD) ? __expf(v - m) : 0.f;
    float s = e;
#pragma unroll
    for (int o = 16; o; o >>= 1) s += __shfl_xor_sync(0xffffffffu, s, o);
    float p = e * (1.f / s);
    if (lane < MOD && write_tail) out_tail[r * MOD + lane] = p;

    int q = (lane < MOD) ? lane : 0;
    float re = 0.f, im = 0.f;
    int t = 0;
#pragma unroll
    for (int k = 0; k < MOD; ++k) {
        float pk = __shfl_sync(0xffffffffu, p, k);
        re = fmaf(pk, sc[t], re);
        im = fmaf(-pk, ss[t], im);
        t += q; if (t >= MOD) t -= MOD;
    }
    if (lane < MOD) g_G2[r * MOD + lane] = make_float2(re, im);
}

// ---------------------------------------------------------------------------
// Kernel 2: chain. Block = one i x 64 b, 256 threads. Four threads per (b,i)
// chain, bins split by quarters with starts {0,4,7,10}. Per-(quarter,p) LUT
// packs 4 byte-offsets. SoA G (conflict-free LDS.32). Threshold early-exit
// (provably safe, see EXIT_TH2) checked every 2 steps. Epilogue streams bins
// via shfl into 13 c-accumulators with immediate twiddles.
// ---------------------------------------------------------------------------
__global__ void __launch_bounds__(256, 7)
chain_kernel(const int* __restrict__ P, float* __restrict__ out) {
    __shared__ float    sG[2 * NN * 32];   // re at [l*32+s], im at +2048 floats
    __shared__ unsigned sP[16 * 64];       // [l/4][b_local]
    __shared__ unsigned sIdx[4 * 26];      // [q*26+p]: 4 packed byte-offsets
    __shared__ float    sOut[64 * 28];

    int tid = threadIdx.x;
    int i   = blockIdx.x >> 4;
    int b0  = (blockIdx.x & 15) << 6;

    if (tid < 104) {
        int q = tid / 26, p = tid - q * 26;
        int js = (q * 10 + 2) / 3;          // {0,4,7,10}
        unsigned v = 0;
#pragma unroll
        for (int k = 0; k < 4; ++k)
            v |= (unsigned)((((js + k) * p) % MOD) * 4) << (8 * k);
        sIdx[tid] = v;
    }
    for (int m = tid; m < NN * 32; m += 256) {
        int l = m >> 5, s = m & 31;
        if (s < MOD) {
            float2 g = g_G2[((l << 6) | i) * MOD + s];
            sG[m] = g.x; sG[2048 + m] = g.y;
        }
    }
    for (int m = tid; m < 1024; m += 256) {
        int bl = m & 63, l4 = m >> 6;
        int4 pv = *reinterpret_cast<const int4*>(P + ((b0 + bl) << 6) + (l4 << 2));
        sP[(l4 << 6) + bl] = (unsigned)pv.x | ((unsigned)pv.y << 8) |
                             ((unsigned)pv.z << 16) | ((unsigned)pv.w << 24);
    }
    __syncthreads();

    int bl = tid >> 2;
    int q  = tid & 3;
    int hq = q * 26;

    float ar[4], ai[4];
    unsigned w = sP[bl];

    { // l = 0 init
        unsigned idx = sIdx[hq + (w & 255u)];
#pragma unroll
        for (int k = 0; k < 4; ++k) {
            unsigned off = (idx >> (8 * k)) & 255u;
            const float* gp = (const float*)((const char*)sG + off);
            ar[k] = gp[0]; ai[k] = gp[2048];
        }
    }

    auto step = [&](int l, unsigned p) {
        unsigned idx = sIdx[hq + p];
        const char* base = (const char*)sG + (l << 7);
#pragma unroll
        for (int k = 0; k < 4; ++k) {
            unsigned off = (idx >> (8 * k)) & 255u;
            const float* gp = (const float*)(base + off);
            float gr = gp[0];
            float gi = gp[2048];
            float nr = fmaf(ar[k], gr, -ai[k] * gi);
            float ni = fmaf(ar[k], gi,  ai[k] * gr);
            ar[k] = nr; ai[k] = ni;
        }
    };

    // True iff every non-DC bin in the warp has |bin| < ~1e-8 (conservative
    // OR-of-bits bound; quarter0's k=0 is the never-small DC bin, masked).
    auto below = [&]() -> bool {
        unsigned nz = __float_as_uint(ar[1]) | __float_as_uint(ai[1]) |
                      __float_as_uint(ar[2]) | __float_as_uint(ai[2]) |
                      __float_as_uint(ar[3]) | __float_as_uint(ai[3]);
        unsigned nz0 = __float_as_uint(ar[0]) | __float_as_uint(ai[0]);
        nz |= q ? nz0 : 0u;
        return __all_sync(0xffffffffu, (nz << 1) < EXIT_TH2);
    };

    step(1, (w >> 8) & 255u);
    step(2, (w >> 16) & 255u);
    step(3, (w >> 24) & 255u);

    bool exited = false;
#pragma unroll 1
    for (int lb = 1; lb < 16; ++lb) {
        if (below()) { exited = true; break; }
        w = sP[(lb << 6) + bl];
        step(lb * 4 + 0,  w        & 255u);
        step(lb * 4 + 1, (w >> 8)  & 255u);
        if (below()) { exited = true; break; }
        step(lb * 4 + 2, (w >> 16) & 255u);
        step(lb * 4 + 3, (w >> 24) & 255u);
    }

    int lane  = tid & 31;
    int half  = q & 1;
    float* so = sOut + bl * 28 + half * 13;

    if (exited) {
        if (q < 2) {
            float val = __logf(1.0f / 26.0f + 1e-12f);
#pragma unroll
            for (int c0 = 0; c0 < 13; ++c0) so[c0] = val;
        }
    } else {
        unsigned gb = lane & ~3u;
        float sg = half ? -1.f : 1.f;
        float v[13];

        // j = 0 (DC, owner q0 k0): coefficient 1, imag exactly 0.
        float b0r = __shfl_sync(0xffffffffu, ar[0], gb);
#pragma unroll
        for (int c0 = 0; c0 < 13; ++c0) v[c0] = b0r;

        // j = 1..12: coefficient 2; odd-j pre-negated for the c+13 half.
#define EPI_J(J, QJ, KJ)                                                      \
        {                                                                     \
            float r_ = __shfl_sync(0xffffffffu, ar[KJ], gb + QJ);             \
            float i_ = __shfl_sync(0xffffffffu, ai[KJ], gb + QJ);             \
            if ((J) & 1) { r_ *= sg; i_ *= sg; }                              \
            _Pragma("unroll")                                                 \
            for (int c0 = 0; c0 < 13; ++c0) {                                 \
                v[c0] = fmaf(r_,  2.f * H_COS[((J) * c0) % MOD], v[c0]);      \
                v[c0] = fmaf(i_, -2.f * H_SIN[((J) * c0) % MOD], v[c0]);      \
            }                                                                 \
        }
        EPI_J(1, 0, 1)  EPI_J(2, 0, 2)  EPI_J(3, 0, 3)
        EPI_J(4, 1, 0)  EPI_J(5, 1, 1)  EPI_J(6, 1, 2)  EPI_J(7, 1, 3)
        EPI_J(8, 2, 1)  EPI_J(9, 2, 2)  EPI_J(10, 2, 3)
        EPI_J(11, 3, 1) EPI_J(12, 3, 2)
#undef EPI_J
        // j = 13 (Nyquist, owner q3 k3): coefficient 1, cos = +/-1, sin = 0.
        {
            float r13 = __shfl_sync(0xffffffffu, ar[3], gb + 3) * sg;
#pragma unroll
            for (int c0 = 0; c0 < 13; ++c0)
                v[c0] += (c0 & 1) ? -r13 : r13;
        }

        if (q < 2) {
            float inv = 1.f / (26.f * b0r);
#pragma unroll
            for (int c0 = 0; c0 < 13; ++c0)
                so[c0] = __logf(fmaf(v[c0], inv, 1e-12f));
        }
    }
    __syncthreads();

    // Coalesced writeout: 8 warps x 8 rows, lanes 0..25 per 104B row.
    int warp = tid >> 5;
    if (lane < MOD) {
#pragma unroll 1
        for (int k = 0; k < 8; ++k) {
            int r = (warp << 3) + k;
            out[(((b0 + r) << 6) | i) * MOD + lane] = sOut[r * 28 + lane];
        }
    }
}

// ---------------------------------------------------------------------------
extern "C" void kernel_launch(void* const* d_in, const int* in_sizes, int n_in,
                              void* d_out, int out_size) {
    const int*   P         = (const int*)d_in[0];    // (1024, 64) int32
    const float* key_param = (const float*)d_in[1];  // (4096, 26) f32
    float*       out       = (float*)d_out;

    const int log_elems = BB * NN * MOD;             // 1,703,936
    const int kp_elems  = NROWS * MOD;               // 106,496
    int write_tail = (out_size >= log_elems + kp_elems) ? 1 : 0;

    prep_kernel<<<NROWS / 4, 128>>>(key_param, out + log_elems, write_tail);
    chain_kernel<<<1024, 256>>>(P, out);
}